// round 5
// baseline (speedup 1.0000x reference)
#include <cuda_runtime.h>
#include <math.h>
#include <stdint.h>

#define NN 50000
#define DD 128
#define EE 800000

// ---------------- device scratch (static, allocation-free) ----------------
__device__ __align__(16) float g_h[NN * DD];     // GEMM output / attention input
__device__ __align__(16) float g_att[NN * DD];   // attention output (gather)
__device__ __align__(16) float g_ss[EE];         // edge scores in slot order
__device__ int g_cnt[NN];                        // per-row degree
__device__ int g_pos[NN];                        // placement cursors
__device__ int g_indptr[NN + 1];                 // CSR row pointers
__device__ int g_ecol[EE];                       // CSR column ids (slot order)
__device__ unsigned g_maxbits[2];                // encoded global max per layer
__device__ float    g_Z[2];                      // softmax denominator per layer

__device__ __forceinline__ unsigned fenc(float f) {
    unsigned b = __float_as_uint(f);
    return (b & 0x80000000u) ? ~b : (b | 0x80000000u);
}
__device__ __forceinline__ float fdec(unsigned u) {
    return (u & 0x80000000u) ? __uint_as_float(u & 0x7FFFFFFFu)
                             : __uint_as_float(~u);
}

// ---------------- CSR build ----------------
__global__ void reset_kernel() {
    int tid = blockIdx.x * blockDim.x + threadIdx.x;
    for (int i = tid; i < NN; i += gridDim.x * blockDim.x) g_cnt[i] = 0;
    if (tid == 0) {
        g_maxbits[0] = fenc(-INFINITY);
        g_maxbits[1] = fenc(-INFINITY);
        g_Z[0] = 0.f;
        g_Z[1] = 0.f;
    }
}

__global__ void hist_kernel(const int* __restrict__ row, int E) {
    int e = blockIdx.x * blockDim.x + threadIdx.x;
    if (e < E) atomicAdd(&g_cnt[__ldg(row + e)], 1);
}

// single-block exclusive scan over g_cnt -> g_indptr, zero g_pos
__global__ void scan_kernel() {
    __shared__ int spart[1024];
    const int t = threadIdx.x;
    const int chunk = (NN + 1023) / 1024;   // 49
    int start = t * chunk;
    int end = start + chunk; if (end > NN) end = NN;
    if (start > NN) start = NN;
    int s = 0;
    for (int i = start; i < end; i++) s += g_cnt[i];
    spart[t] = s;
    __syncthreads();
    for (int off = 1; off < 1024; off <<= 1) {
        int v = (t >= off) ? spart[t - off] : 0;
        __syncthreads();
        spart[t] += v;
        __syncthreads();
    }
    int run = (t == 0) ? 0 : spart[t - 1];
    for (int i = start; i < end; i++) {
        g_indptr[i] = run;
        g_pos[i] = 0;
        run += g_cnt[i];
    }
    if (t == 1023) g_indptr[NN] = spart[1023];
}

__global__ void place_kernel(const int* __restrict__ row, const int* __restrict__ col, int E) {
    int e = blockIdx.x * blockDim.x + threadIdx.x;
    if (e < E) {
        int r = __ldg(row + e);
        int slot = g_indptr[r] + atomicAdd(&g_pos[r], 1);
        g_ecol[slot] = __ldg(col + e);
    }
}

// ---------------- GEMM: C = act(scale*A @ W + bias), K=N=128 ----------------
#define GEMM_SMEM ((64 * 128 + 128 * 128) * 4)

template <bool RELU>
__global__ __launch_bounds__(128)
void gemm128(const float* __restrict__ A, const float* __restrict__ W,
             const float* __restrict__ bias, float* __restrict__ C,
             int M, const float* __restrict__ zptr) {
    extern __shared__ float sm[];
    float4* As4 = reinterpret_cast<float4*>(sm);             // 64*32 float4
    float4* Ws4 = reinterpret_cast<float4*>(sm + 64 * 128);  // 128*32 float4

    const int tid = threadIdx.x;
    const int tx = tid & 15;
    const int ty = tid >> 4;
    const int base = blockIdx.x * 64;

    const float scale = zptr ? (1.0f / (*zptr)) : 1.0f;

    const float4* Wg = reinterpret_cast<const float4*>(W);
#pragma unroll
    for (int i = 0; i < 32; i++) Ws4[tid + i * 128] = Wg[tid + i * 128];

    const float4* Ag = reinterpret_cast<const float4*>(A);
#pragma unroll
    for (int i = 0; i < 16; i++) {
        int f = tid + i * 128;
        int r = f >> 5;
        int c = f & 31;
        float4 v = make_float4(0.f, 0.f, 0.f, 0.f);
        if (base + r < M) v = Ag[(base + r) * 32 + c];
        v.x *= scale; v.y *= scale; v.z *= scale; v.w *= scale;
        As4[r * 32 + c] = v;
    }
    __syncthreads();

    float acc[8][8];
#pragma unroll
    for (int i = 0; i < 8; i++)
#pragma unroll
        for (int j = 0; j < 8; j++) acc[i][j] = 0.f;

#pragma unroll 4
    for (int kc = 0; kc < 32; kc++) {
        float4 a4[8];
#pragma unroll
        for (int i = 0; i < 8; i++) a4[i] = As4[(ty * 8 + i) * 32 + kc];
#pragma unroll
        for (int q = 0; q < 4; q++) {
            int k = kc * 4 + q;
            float4 b0 = Ws4[k * 32 + tx];
            float4 b1 = Ws4[k * 32 + 16 + tx];
#pragma unroll
            for (int i = 0; i < 8; i++) {
                float a = (q == 0) ? a4[i].x : (q == 1) ? a4[i].y
                        : (q == 2) ? a4[i].z : a4[i].w;
                acc[i][0] += a * b0.x; acc[i][1] += a * b0.y;
                acc[i][2] += a * b0.z; acc[i][3] += a * b0.w;
                acc[i][4] += a * b1.x; acc[i][5] += a * b1.y;
                acc[i][6] += a * b1.z; acc[i][7] += a * b1.w;
            }
        }
    }

    const float4 bb0 = reinterpret_cast<const float4*>(bias)[tx];
    const float4 bb1 = reinterpret_cast<const float4*>(bias)[16 + tx];
    float4* Cg = reinterpret_cast<float4*>(C);
#pragma unroll
    for (int i = 0; i < 8; i++) {
        int row = base + ty * 8 + i;
        if (row >= M) break;
        float4 o0 = make_float4(acc[i][0] + bb0.x, acc[i][1] + bb0.y,
                                acc[i][2] + bb0.z, acc[i][3] + bb0.w);
        float4 o1 = make_float4(acc[i][4] + bb1.x, acc[i][5] + bb1.y,
                                acc[i][6] + bb1.z, acc[i][7] + bb1.w);
        if (RELU) {
            o0.x = fmaxf(o0.x, 0.f); o0.y = fmaxf(o0.y, 0.f);
            o0.z = fmaxf(o0.z, 0.f); o0.w = fmaxf(o0.w, 0.f);
            o1.x = fmaxf(o1.x, 0.f); o1.y = fmaxf(o1.y, 0.f);
            o1.z = fmaxf(o1.z, 0.f); o1.w = fmaxf(o1.w, 0.f);
        }
        Cg[row * 32 + tx] = o0;
        Cg[row * 32 + 16 + tx] = o1;
    }
}

// ---------------- score: warp per node, h[row] in registers ----------------
__global__ __launch_bounds__(256)
void score_gather(const float* __restrict__ h, int layer) {
    const int node = (blockIdx.x * blockDim.x + threadIdx.x) >> 5;
    const int lane = threadIdx.x & 31;
    const int wid = threadIdx.x >> 5;
    float m = -INFINITY;
    if (node < NN) {
        const float4* h4 = reinterpret_cast<const float4*>(h);
        const float4 q = __ldg(h4 + node * 32 + lane);
        const int beg = g_indptr[node];
        const int end = g_indptr[node + 1];
        for (int j = beg; j < end; j++) {
            int c = g_ecol[j];
            float4 b = __ldg(h4 + c * 32 + lane);
            float s = q.x * b.x + q.y * b.y + q.z * b.z + q.w * b.w;
#pragma unroll
            for (int o = 16; o; o >>= 1) s += __shfl_xor_sync(0xFFFFFFFFu, s, o);
            float d = (s > 0.f) ? s : 0.2f * s;
            if (lane == 0) g_ss[j] = d;
            m = fmaxf(m, d);
        }
    }
    __shared__ float smax[8];
    if (lane == 0) smax[wid] = m;
    __syncthreads();
    if (threadIdx.x == 0) {
        float mm = smax[0];
#pragma unroll
        for (int i = 1; i < 8; i++) mm = fmaxf(mm, smax[i]);
        if (mm > -INFINITY) atomicMax(&g_maxbits[layer], fenc(mm));
    }
}

// ---------------- aggregate: warp per node, register accumulation ----------
__global__ __launch_bounds__(256)
void agg_gather(const float* __restrict__ h, float* __restrict__ out, int layer) {
    const int node = (blockIdx.x * blockDim.x + threadIdx.x) >> 5;
    const int lane = threadIdx.x & 31;
    const int wid = threadIdx.x >> 5;
    float z = 0.f;
    if (node < NN) {
        const float m = fdec(g_maxbits[layer]);
        const float4* h4 = reinterpret_cast<const float4*>(h);
        float4 acc = make_float4(0.f, 0.f, 0.f, 0.f);
        const int beg = g_indptr[node];
        const int end = g_indptr[node + 1];
        for (int j = beg; j < end; j++) {
            float p = __expf(__ldg(g_ss + j) - m);
            int c = g_ecol[j];
            float4 v = __ldg(h4 + c * 32 + lane);
            acc.x += p * v.x; acc.y += p * v.y;
            acc.z += p * v.z; acc.w += p * v.w;
            if (lane == 0) z += p;
        }
        reinterpret_cast<float4*>(out)[node * 32 + lane] = acc;
    }
    __shared__ float sZ[8];
    if (lane == 0) sZ[wid] = z;
    __syncthreads();
    if (threadIdx.x == 0) {
        float zz = 0.f;
#pragma unroll
        for (int i = 0; i < 8; i++) zz += sZ[i];
        atomicAdd(&g_Z[layer], zz);
    }
}

// ---------------- host launch sequence ----------------
extern "C" void kernel_launch(void* const* d_in, const int* in_sizes, int n_in,
                              void* d_out, int out_size) {
    const float* x  = (const float*)d_in[0];
    const int*   ei = (const int*)d_in[1];
    const float* W0 = (const float*)d_in[2];
    const float* b0 = (const float*)d_in[3];
    const float* W1 = (const float*)d_in[4];
    const float* b1 = (const float*)d_in[5];
    const float* W2 = (const float*)d_in[6];
    const float* b2 = (const float*)d_in[7];

    int M = in_sizes[0] / DD;
    int E = in_sizes[1] / 2;
    if (M > NN) M = NN;
    if (E > EE) E = EE;
    const int* row = ei;
    const int* col = ei + E;

    void *ph, *pa, *pz;
    cudaGetSymbolAddress(&ph, g_h);
    cudaGetSymbolAddress(&pa, g_att);
    cudaGetSymbolAddress(&pz, g_Z);
    float* h   = (float*)ph;
    float* att = (float*)pa;
    float* Z   = (float*)pz;

    cudaFuncSetAttribute(gemm128<true>, cudaFuncAttributeMaxDynamicSharedMemorySize, GEMM_SMEM);
    cudaFuncSetAttribute(gemm128<false>, cudaFuncAttributeMaxDynamicSharedMemorySize, GEMM_SMEM);

    const int gG = (M + 63) / 64;               // gemm grid
    const int gN = (NN + 7) / 8;                // node grid (8 warps/block)
    const int gEb = (E + 255) / 256;            // edge grid

    // ---- CSR build (once per call) ----
    reset_kernel<<<256, 256>>>();
    hist_kernel<<<gEb, 256>>>(row, E);
    scan_kernel<<<1, 1024>>>();
    place_kernel<<<gEb, 256>>>(row, col, E);

    // ---- layer 0 ----
    gemm128<true><<<gG, 128, GEMM_SMEM>>>(x, W0, b0, h, M, nullptr);
    score_gather<<<gN, 256>>>(h, 0);
    agg_gather<<<gN, 256>>>(h, att, 0);

    // ---- layer 1 (fold 1/Z0 into A-load) ----
    gemm128<true><<<gG, 128, GEMM_SMEM>>>(att, W1, b1, h, M, Z + 0);
    score_gather<<<gN, 256>>>(h, 1);
    agg_gather<<<gN, 256>>>(h, att, 1);

    // ---- output layer (fold 1/Z1, no relu) ----
    gemm128<false><<<gG, 128, GEMM_SMEM>>>(att, W2, b2, (float*)d_out, M, Z + 1);
}